// round 2
// baseline (speedup 1.0000x reference)
#include <cuda_runtime.h>
#include <cstdint>

// Problem constants (fixed by the dataset)
#define Nn  50000
#define Ee  800000
#define NGg 128
#define Dd  128
#define Mm  2

// ---------------- scratch (device globals; no allocation allowed) ----------------
__device__ float g_tx[Nn * Dd];            // encoded node features
__device__ float g_h[Mm * Nn * Dd];        // current hidden state (pass 1 uses first N rows)
__device__ float g_agg[Mm * Nn * Dd];      // aggregation buffer
__device__ int   g_deg[Nn];
__device__ int   g_rowptr[Nn + 1];
__device__ int   g_cursor[Nn];
__device__ int   g_col[Ee];                // CSR by dst: src indices
__device__ float g_pred[Nn];
__device__ float g_e[Nn];
__device__ unsigned g_mxbits[NGg];
__device__ float g_ssum[NGg];
__device__ unsigned g_mx2bits[Mm * NGg];
__device__ int   g_raw[Mm * NGg];
__device__ int   g_counts[NGg];
__device__ unsigned char g_flag[Mm * Nn];
__device__ float g_score[Mm * Nn];
__device__ float g_hg[Mm * NGg * Dd];      // pooled graph embeddings (sums)

// ---------------- threefry2x32 (exact JAX semantics) ----------------
static __host__ __device__ inline unsigned rotl32(unsigned v, int r) {
    return (v << r) | (v >> (32 - r));
}
static __host__ __device__ inline void tf2x32(unsigned k0, unsigned k1,
                                              unsigned& x0, unsigned& x1) {
    unsigned k2 = k0 ^ k1 ^ 0x1BD11BDAu;
    x0 += k0; x1 += k1;
#define TFR(r) { x0 += x1; x1 = rotl32(x1, (r)); x1 ^= x0; }
    TFR(13) TFR(15) TFR(26) TFR(6)
    x0 += k1; x1 += k2 + 1u;
    TFR(17) TFR(29) TFR(16) TFR(24)
    x0 += k2; x1 += k0 + 2u;
    TFR(13) TFR(15) TFR(26) TFR(6)
    x0 += k0; x1 += k1 + 3u;
    TFR(17) TFR(29) TFR(16) TFR(24)
    x0 += k1; x1 += k2 + 4u;
    TFR(13) TFR(15) TFR(26) TFR(6)
    x0 += k2; x1 += k0 + 5u;
#undef TFR
}

// order-preserving float<->uint mapping for atomic max on floats
static __device__ inline unsigned encf(float f) {
    unsigned u = __float_as_uint(f);
    return (u & 0x80000000u) ? ~u : (u | 0x80000000u);
}
static __device__ inline float decf(unsigned u) {
    u = (u & 0x80000000u) ? (u & 0x7FFFFFFFu) : ~u;
    return __uint_as_float(u);
}

// ---------------- kernels ----------------
__global__ void k_reset() {
    int i = blockIdx.x * blockDim.x + threadIdx.x;
    if (i < Mm * Nn) g_flag[i] = 0;
    if (i < Nn) { g_deg[i] = 0; g_cursor[i] = 0; }
    if (i < Mm * NGg * Dd) g_hg[i] = 0.f;
    if (i < NGg) { g_counts[i] = 0; g_mxbits[i] = 0u; g_ssum[i] = 0.f; }
    if (i < Mm * NGg) { g_mx2bits[i] = 0u; g_raw[i] = Nn; }
}

__global__ void k_hist(const int* __restrict__ edst) {
    int e = blockIdx.x * blockDim.x + threadIdx.x;
    if (e < Ee) atomicAdd(&g_deg[edst[e]], 1);
}

__global__ void k_scan() {
    __shared__ int ss[1024];
    int tid = threadIdx.x;
    const int CH = (Nn + 1023) / 1024;
    int beg = tid * CH;
    int end = beg + CH; if (end > Nn) end = Nn;
    int s = 0;
    for (int i = beg; i < end; i++) s += g_deg[i];
    ss[tid] = s;
    __syncthreads();
    for (int off = 1; off < 1024; off <<= 1) {
        int v = (tid >= off) ? ss[tid - off] : 0;
        __syncthreads();
        ss[tid] += v;
        __syncthreads();
    }
    int base = (tid == 0) ? 0 : ss[tid - 1];
    for (int i = beg; i < end; i++) { g_rowptr[i] = base; base += g_deg[i]; }
    if (tid == 1023) g_rowptr[Nn] = ss[1023];
}

__global__ void k_fill(const int* __restrict__ esrc, const int* __restrict__ edst) {
    int e = blockIdx.x * blockDim.x + threadIdx.x;
    if (e >= Ee) return;
    int d = edst[e];
    int p = atomicAdd(&g_cursor[d], 1);
    g_col[g_rowptr[d] + p] = esrc[e];
}

__global__ void k_embed(const int* __restrict__ x_idx, const float* __restrict__ x_table,
                        const int* __restrict__ batch) {
    int idx = blockIdx.x * blockDim.x + threadIdx.x;
    if (idx >= Nn * 32) return;
    int n = idx >> 5, q = idx & 31;
    int xi = x_idx[n];
    float4 v = *(const float4*)(x_table + (size_t)xi * Dd + q * 4);
    *(float4*)(g_tx + (size_t)n * Dd + q * 4) = v;
    if (q == 0) atomicAdd(&g_counts[batch[n]], 1);
}

// one warp per (m, node); lane handles 4 contiguous floats
__global__ void k_agg(int in_is_tx, int total) {
    int w = (blockIdx.x * blockDim.x + threadIdx.x) >> 5;
    if (w >= total) return;
    int lane = threadIdx.x & 31;
    int m = w / Nn;
    int n = w - m * Nn;
    const float* hb = (in_is_tx ? g_tx : g_h) + (size_t)m * Nn * Dd;
    int e = g_rowptr[n], end = g_rowptr[n + 1];
    float4 acc = make_float4(0.f, 0.f, 0.f, 0.f);
    for (; e + 1 < end; e += 2) {
        int s0 = g_col[e], s1 = g_col[e + 1];
        float4 v0 = *(const float4*)(hb + (size_t)s0 * Dd + lane * 4);
        float4 v1 = *(const float4*)(hb + (size_t)s1 * Dd + lane * 4);
        acc.x += v0.x + v1.x; acc.y += v0.y + v1.y;
        acc.z += v0.z + v1.z; acc.w += v0.w + v1.w;
    }
    if (e < end) {
        int s0 = g_col[e];
        float4 v0 = *(const float4*)(hb + (size_t)s0 * Dd + lane * 4);
        acc.x += v0.x; acc.y += v0.y; acc.z += v0.z; acc.w += v0.w;
    }
    *(float4*)(g_agg + (size_t)w * Dd + lane * 4) = acc;
}

// [rows,128] @ [128,128] + bias, relu; optional agg added to input, optional
// pooled atomic output instead of dense output. 64 rows x 128 cols per block.
__global__ __launch_bounds__(256) void k_gemm(
    int in_is_tx, int use_agg, int use_out, int use_pool,
    const float* __restrict__ W, const float* __restrict__ bias,
    const int* __restrict__ batch, int rows)
{
    __shared__ float sW[32 * 128];
    __shared__ float sIn[64 * 33];
    const float* in = in_is_tx ? g_tx : g_h;
    int t = threadIdx.x;
    int rg = t >> 4, cg = t & 15;
    int row0 = blockIdx.x * 64;
    float acc[4][8];
#pragma unroll
    for (int r = 0; r < 4; r++)
#pragma unroll
        for (int j = 0; j < 8; j++) acc[r][j] = 0.f;

    for (int kc = 0; kc < 4; kc++) {
        const float4* W4 = (const float4*)(W + kc * 32 * 128);
        float4* sW4 = (float4*)sW;
#pragma unroll
        for (int i = 0; i < 4; i++) sW4[t + 256 * i] = W4[t + 256 * i];
#pragma unroll
        for (int i2 = 0; i2 < 2; i2++) {
            int i = t + 256 * i2;
            int r = i >> 3, k4 = i & 7;
            int grow = row0 + r;
            float4 v = make_float4(0.f, 0.f, 0.f, 0.f);
            if (grow < rows) {
                v = *(const float4*)(in + (size_t)grow * Dd + kc * 32 + k4 * 4);
                if (use_agg) {
                    float4 a = *(const float4*)(g_agg + (size_t)grow * Dd + kc * 32 + k4 * 4);
                    v.x += a.x; v.y += a.y; v.z += a.z; v.w += a.w;
                }
            }
            int kk = k4 * 4;
            sIn[r * 33 + kk + 0] = v.x;
            sIn[r * 33 + kk + 1] = v.y;
            sIn[r * 33 + kk + 2] = v.z;
            sIn[r * 33 + kk + 3] = v.w;
        }
        __syncthreads();
#pragma unroll
        for (int kk = 0; kk < 32; kk++) {
            float a[4], w[8];
#pragma unroll
            for (int r = 0; r < 4; r++) a[r] = sIn[(rg + 16 * r) * 33 + kk];
#pragma unroll
            for (int j = 0; j < 8; j++) w[j] = sW[kk * 128 + cg + 16 * j];
#pragma unroll
            for (int r = 0; r < 4; r++)
#pragma unroll
                for (int j = 0; j < 8; j++) acc[r][j] = fmaf(a[r], w[j], acc[r][j]);
        }
        __syncthreads();
    }
#pragma unroll
    for (int r = 0; r < 4; r++) {
        int grow = row0 + rg + 16 * r;
        if (grow >= rows) continue;
        if (use_out) {
#pragma unroll
            for (int j = 0; j < 8; j++) {
                float v = fmaxf(acc[r][j] + bias[cg + 16 * j], 0.f);
                g_h[(size_t)grow * Dd + cg + 16 * j] = v;
            }
        }
        if (use_pool) {
            int m = grow / Nn;
            int n = grow - m * Nn;
            int g = batch[n];
            float* pb = g_hg + ((size_t)m * NGg + g) * Dd;
#pragma unroll
            for (int j = 0; j < 8; j++) {
                float v = fmaxf(acc[r][j] + bias[cg + 16 * j], 0.f);
                atomicAdd(pb + cg + 16 * j, v);
            }
        }
    }
}

__global__ void k_pred(const float* __restrict__ Wd, const float* __restrict__ bd) {
    int w = (blockIdx.x * blockDim.x + threadIdx.x) >> 5;
    if (w >= Nn) return;
    int lane = threadIdx.x & 31;
    float4 hv = *(const float4*)(g_h + (size_t)w * Dd + lane * 4);
    float4 wv = *(const float4*)(Wd + lane * 4);
    float s = hv.x * wv.x + hv.y * wv.y + hv.z * wv.z + hv.w * wv.w;
#pragma unroll
    for (int o = 16; o > 0; o >>= 1) s += __shfl_xor_sync(0xffffffffu, s, o);
    if (lane == 0) g_pred[w] = s + bd[0];
}

__global__ void k_segmax(const int* __restrict__ batch) {
    int n = blockIdx.x * blockDim.x + threadIdx.x;
    if (n >= Nn) return;
    atomicMax(&g_mxbits[batch[n]], encf(g_pred[n]));
}

__global__ void k_segexp(const int* __restrict__ batch) {
    int n = blockIdx.x * blockDim.x + threadIdx.x;
    if (n >= Nn) return;
    int g = batch[n];
    float e = expf(g_pred[n] - decf(g_mxbits[g]));
    g_e[n] = e;
    atomicAdd(&g_ssum[g], e);
}

// logp + gumbel per (m,n); JAX partitionable threefry: bits = low word of
// threefry(key, hi=0, lo=flat_index)
__global__ void k_score(const int* __restrict__ batch, unsigned fk0, unsigned fk1) {
    int n = blockIdx.x * blockDim.x + threadIdx.x;
    if (n >= Nn) return;
    int g = batch[n];
    float p = g_e[n] / g_ssum[g];
    float lp = logf(p + 1e-15f);
#pragma unroll
    for (int m = 0; m < Mm; m++) {
        unsigned x0 = 0u, x1 = (unsigned)(m * Nn + n);
        tf2x32(fk0, fk1, x0, x1);
        unsigned bits = x1;  // RNG VARIANT: partitionable (64-bit word truncated low)
        float u = __uint_as_float((bits >> 9) | 0x3F800000u) - 1.0f;
        u = fmaxf(u, 0.0f);
        float gum = -logf(-logf(u + 1e-12f) + 1e-12f);
        float sc = lp + gum;
        g_score[m * Nn + n] = sc;
        atomicMax(&g_mx2bits[m * NGg + g], encf(sc));
    }
}

__global__ void k_argmin(const int* __restrict__ batch) {
    int idx = blockIdx.x * blockDim.x + threadIdx.x;
    if (idx >= Mm * Nn) return;
    int m = idx / Nn;
    int n = idx - m * Nn;
    int g = batch[n];
    float sc = g_score[idx];
    float mx = decf(g_mx2bits[m * NGg + g]);
    int cand = (sc >= mx) ? n : Nn;
    atomicMin(&g_raw[m * NGg + g], cand);
}

__global__ void k_buildflag() {
    int i = threadIdx.x;
    if (i >= Mm * NGg) return;
    int r = g_raw[i];
    if (r < Nn) g_flag[(i / NGg) * Nn + r] = 1;
}

__global__ void k_buildx(const float* __restrict__ anchor_table) {
    int idx = blockIdx.x * blockDim.x + threadIdx.x;
    if (idx >= Mm * Nn * 32) return;
    int q = idx & 31;
    int mn = idx >> 5;
    int n = mn % Nn;
    float4 tv = *(const float4*)(g_tx + (size_t)n * Dd + q * 4);
    if (g_flag[mn]) {
        const float4 av = *(const float4*)(anchor_table + Dd + q * 4);  // row 1
        tv.x = fmaf(tv.x, av.x, tv.x);
        tv.y = fmaf(tv.y, av.y, tv.y);
        tv.z = fmaf(tv.z, av.z, tv.z);
        tv.w = fmaf(tv.w, av.w, tv.w);
    }
    *(float4*)(g_h + (size_t)mn * Dd + q * 4) = tv;
}

__global__ void k_final(const float* __restrict__ Wp, const float* __restrict__ bp,
                        float* __restrict__ out) {
    __shared__ float red[128];
    int g = blockIdx.x, t = threadIdx.x;
    int c = g_counts[g]; if (c < 1) c = 1;
    float inv = 1.0f / (float)c;
    float hsum = (g_hg[(size_t)g * Dd + t] + g_hg[((size_t)NGg + g) * Dd + t]) * inv;
    for (int tt = 0; tt < 10; tt++) {
        red[t] = hsum * Wp[t * 10 + tt];
        __syncthreads();
        for (int off = 64; off > 0; off >>= 1) {
            if (t < off) red[t] += red[t + off];
            __syncthreads();
        }
        if (t == 0) out[g * 10 + tt] = red[0] * 0.5f + bp[tt];
        __syncthreads();
    }
}

// ---------------- launch ----------------
static inline int cdiv(int a, int b) { return (a + b - 1) / b; }

extern "C" void kernel_launch(void* const* d_in, const int* in_sizes, int n_in,
                              void* d_out, int out_size) {
    const int*   x_idx        = (const int*)d_in[0];
    const int*   esrc         = (const int*)d_in[1];
    const int*   edst         = (const int*)d_in[2];
    const int*   batch        = (const int*)d_in[3];
    const float* x_table      = (const float*)d_in[4];
    const float* anchor_table = (const float*)d_in[5];
    const float* Wg           = (const float*)d_in[6];
    const float* bg           = (const float*)d_in[7];
    const float* Wn           = (const float*)d_in[8];
    const float* bn           = (const float*)d_in[9];
    const float* Wd           = (const float*)d_in[10];
    const float* bd           = (const float*)d_in[11];
    const float* Wp           = (const float*)d_in[12];
    const float* bp           = (const float*)d_in[13];
    float* out = (float*)d_out;

    // fold_in(key(1), 1) on host: threefry(key=(0,1), count=(0,1)) -> new key
    unsigned fk0 = 0u, fk1 = 1u;
    tf2x32(0u, 1u, fk0, fk1);

    // setup: CSR + embeddings + resets
    k_reset<<<cdiv(Mm * Nn, 256), 256>>>();
    k_hist<<<cdiv(Ee, 256), 256>>>(edst);
    k_scan<<<1, 1024>>>();
    k_fill<<<cdiv(Ee, 256), 256>>>(esrc, edst);
    k_embed<<<cdiv(Nn * 32, 256), 256>>>(x_idx, x_table, batch);

    // first GNN pass (m-independent, single copy)
    k_agg<<<cdiv(Nn * 32, 256), 256>>>(1, Nn);
    k_gemm<<<cdiv(Nn, 64), 256>>>(1, 1, 1, 0, Wg, bg, nullptr, Nn);
    k_agg<<<cdiv(Nn * 32, 256), 256>>>(0, Nn);
    k_gemm<<<cdiv(Nn, 64), 256>>>(0, 1, 1, 0, Wg + Dd * Dd, bg + Dd, nullptr, Nn);

    // anchor sampling
    k_pred<<<cdiv(Nn * 32, 256), 256>>>(Wd, bd);
    k_segmax<<<cdiv(Nn, 256), 256>>>(batch);
    k_segexp<<<cdiv(Nn, 256), 256>>>(batch);
    k_score<<<cdiv(Nn, 256), 256>>>(batch, fk0, fk1);
    k_argmin<<<cdiv(Mm * Nn, 256), 256>>>(batch);
    k_buildflag<<<1, 256>>>();
    k_buildx<<<cdiv(Mm * Nn * 32, 256), 256>>>(anchor_table);

    // second GNN pass (per-m)
    k_agg<<<cdiv(Mm * Nn * 32, 256), 256>>>(0, Mm * Nn);
    k_gemm<<<cdiv(Mm * Nn, 64), 256>>>(0, 1, 1, 0, Wg, bg, nullptr, Mm * Nn);
    k_agg<<<cdiv(Mm * Nn * 32, 256), 256>>>(0, Mm * Nn);
    k_gemm<<<cdiv(Mm * Nn, 64), 256>>>(0, 1, 1, 0, Wg + Dd * Dd, bg + Dd, nullptr, Mm * Nn);

    // node MLP + fused pooling (hn never materialized)
    k_gemm<<<cdiv(Mm * Nn, 64), 256>>>(0, 0, 0, 1, Wn, bn, batch, Mm * Nn);

    // final projection + mean over m
    k_final<<<NGg, 128>>>(Wp, bp, out);
}

// round 3
// speedup vs baseline: 1.1706x; 1.1706x over previous
#include <cuda_runtime.h>
#include <cstdint>

// Problem constants (fixed by the dataset)
#define Nn  50000
#define Ee  800000
#define NGg 128
#define Dd  128
#define Mm  2

// ---------------- scratch (device globals; no allocation allowed) ----------------
__device__ float g_tx[Nn * Dd];            // encoded node features
__device__ float g_xM[Mm * Nn * Dd];       // pass-2 input x' per m
__device__ float g_hA[Mm * Nn * Dd];       // layer-1 outputs (pass1 dual-written, pass2 sparse-patched)
__device__ float g_hB[Mm * Nn * Dd];       // layer-2 outputs (pass 2)
__device__ int   g_deg[Nn];
__device__ int   g_rowptr[Nn + 1];
__device__ int   g_cursor[Nn];
__device__ int   g_col[Ee];                // CSR by dst: src indices
__device__ float g_pred[Nn];
__device__ float g_e[Nn];
__device__ unsigned g_mxbits[NGg];
__device__ float g_ssum[NGg];
__device__ unsigned g_mx2bits[Mm * NGg];
__device__ int   g_raw[Mm * NGg];
__device__ int   g_counts[NGg];
__device__ unsigned char g_flag[Mm * Nn];
__device__ float g_score[Mm * Nn];
__device__ float g_hg[Mm * NGg * Dd];      // pooled graph embeddings (sums)
__device__ int   g_amark[Mm * Nn];         // affected-row dedup marks
__device__ int   g_alist[Mm * Nn];         // affected-row list (global row ids)
__device__ int   g_naff;

// ---------------- threefry2x32 (exact JAX semantics) ----------------
static __host__ __device__ inline unsigned rotl32(unsigned v, int r) {
    return (v << r) | (v >> (32 - r));
}
static __host__ __device__ inline void tf2x32(unsigned k0, unsigned k1,
                                              unsigned& x0, unsigned& x1) {
    unsigned k2 = k0 ^ k1 ^ 0x1BD11BDAu;
    x0 += k0; x1 += k1;
#define TFR(r) { x0 += x1; x1 = rotl32(x1, (r)); x1 ^= x0; }
    TFR(13) TFR(15) TFR(26) TFR(6)
    x0 += k1; x1 += k2 + 1u;
    TFR(17) TFR(29) TFR(16) TFR(24)
    x0 += k2; x1 += k0 + 2u;
    TFR(13) TFR(15) TFR(26) TFR(6)
    x0 += k0; x1 += k1 + 3u;
    TFR(17) TFR(29) TFR(16) TFR(24)
    x0 += k1; x1 += k2 + 4u;
    TFR(13) TFR(15) TFR(26) TFR(6)
    x0 += k2; x1 += k0 + 5u;
#undef TFR
}

static __device__ inline unsigned encf(float f) {
    unsigned u = __float_as_uint(f);
    return (u & 0x80000000u) ? ~u : (u | 0x80000000u);
}
static __device__ inline float decf(unsigned u) {
    u = (u & 0x80000000u) ? (u & 0x7FFFFFFFu) : ~u;
    return __uint_as_float(u);
}

// ---------------- small kernels ----------------
__global__ void k_reset() {
    int i = blockIdx.x * blockDim.x + threadIdx.x;
    if (i < Mm * Nn) { g_flag[i] = 0; g_amark[i] = 0; }
    if (i < Nn) { g_deg[i] = 0; g_cursor[i] = 0; }
    if (i < Mm * NGg * Dd) g_hg[i] = 0.f;
    if (i < NGg) { g_counts[i] = 0; g_mxbits[i] = 0u; g_ssum[i] = 0.f; }
    if (i < Mm * NGg) { g_mx2bits[i] = 0u; g_raw[i] = Nn; }
    if (i == 0) g_naff = 0;
}

__global__ void k_hist(const int* __restrict__ edst) {
    int e = blockIdx.x * blockDim.x + threadIdx.x;
    if (e < Ee) atomicAdd(&g_deg[edst[e]], 1);
}

__global__ void k_scan() {
    __shared__ int ss[1024];
    int tid = threadIdx.x;
    const int CH = (Nn + 1023) / 1024;
    int beg = tid * CH;
    int end = beg + CH; if (end > Nn) end = Nn;
    int s = 0;
    for (int i = beg; i < end; i++) s += g_deg[i];
    ss[tid] = s;
    __syncthreads();
    for (int off = 1; off < 1024; off <<= 1) {
        int v = (tid >= off) ? ss[tid - off] : 0;
        __syncthreads();
        ss[tid] += v;
        __syncthreads();
    }
    int base = (tid == 0) ? 0 : ss[tid - 1];
    for (int i = beg; i < end; i++) { g_rowptr[i] = base; base += g_deg[i]; }
    if (tid == 1023) g_rowptr[Nn] = ss[1023];
}

__global__ void k_fill(const int* __restrict__ esrc, const int* __restrict__ edst) {
    int e = blockIdx.x * blockDim.x + threadIdx.x;
    if (e >= Ee) return;
    int d = edst[e];
    int p = atomicAdd(&g_cursor[d], 1);
    g_col[g_rowptr[d] + p] = esrc[e];
}

__global__ void k_embed(const int* __restrict__ x_idx, const float* __restrict__ x_table,
                        const int* __restrict__ batch) {
    int idx = blockIdx.x * blockDim.x + threadIdx.x;
    if (idx >= Nn * 32) return;
    int n = idx >> 5, q = idx & 31;
    int xi = x_idx[n];
    float4 v = *(const float4*)(x_table + (size_t)xi * Dd + q * 4);
    *(float4*)(g_tx + (size_t)n * Dd + q * 4) = v;
    if (q == 0) atomicAdd(&g_counts[batch[n]], 1);
}

// ---------------- fused gather+GEMM(+epilogues) ----------------
// insel: 0=g_tx 1=g_xM 2=g_hA 3=g_hB
// mode : 0 = relu out, dual-write both m slices of g_hA (pass1 L1, rows<Nn)
//        1 = pred epilogue only: g_pred[row] = relu(h)·Wd + bd
//        2 = relu out to (outsel? g_hB : g_hA)
//        3 = relu + smem-staged graph pooling into g_hg (no dense out)
// sparse: rows come from g_alist[0..g_naff)
__global__ __launch_bounds__(256) void k_fused(
    int insel, int gather, int mode, int outsel,
    const float* __restrict__ W, const float* __restrict__ bias,
    const float* __restrict__ Wd, const float* __restrict__ bd,
    const int* __restrict__ batch, int nrows, int sparse)
{
    __shared__ float sIn[64 * 129];
    __shared__ float sW[16 * 128];
    __shared__ int sRow[64];
    const float* in = (insel == 0) ? g_tx : (insel == 1) ? g_xM
                    : (insel == 2) ? g_hA : g_hB;
    int t = threadIdx.x, lane = t & 31, wid = t >> 5;
    int rg = t >> 4, cg = t & 15;
    int total = sparse ? g_naff : nrows;

    for (int tile = blockIdx.x; tile * 64 < total; tile += gridDim.x) {
        if (t < 64) {
            int idx = tile * 64 + t;
            sRow[t] = (idx < total) ? (sparse ? g_alist[idx] : idx) : -1;
        }
        __syncthreads();

        // stage input rows (+ neighbor aggregation) into sIn
        for (int rr = wid; rr < 64; rr += 8) {
            int grow = sRow[rr];
            float4 acc = make_float4(0.f, 0.f, 0.f, 0.f);
            if (grow >= 0) {
                int m = grow / Nn, n = grow - m * Nn;
                const float* base = in + (size_t)m * Nn * Dd;
                acc = *(const float4*)(base + (size_t)n * Dd + lane * 4);
                if (gather) {
                    int beg = g_rowptr[n];
                    int deg = g_rowptr[n + 1] - beg;
                    for (int b0 = 0; b0 < deg; b0 += 32) {
                        int rem = deg - b0;
                        int lim = rem < 32 ? rem : 32;
                        int c = (lane < lim) ? g_col[beg + b0 + lane] : 0;
                        for (int j = 0; j < lim; j++) {
                            int s = __shfl_sync(0xffffffffu, c, j);
                            float4 v = *(const float4*)(base + (size_t)s * Dd + lane * 4);
                            acc.x += v.x; acc.y += v.y; acc.z += v.z; acc.w += v.w;
                        }
                    }
                }
            }
            float* d = &sIn[rr * 129 + lane * 4];
            d[0] = acc.x; d[1] = acc.y; d[2] = acc.z; d[3] = acc.w;
        }
        __syncthreads();

        // 64x128 GEMM, k chunked by 16
        float acc[4][8];
#pragma unroll
        for (int r = 0; r < 4; r++)
#pragma unroll
            for (int j = 0; j < 8; j++) acc[r][j] = 0.f;

        for (int kc = 0; kc < 8; kc++) {
            const float4* Ws = (const float4*)(W + kc * 16 * 128);
            ((float4*)sW)[t] = Ws[t];
            ((float4*)sW)[t + 256] = Ws[t + 256];
            __syncthreads();
#pragma unroll
            for (int kk = 0; kk < 16; kk++) {
                float a[4], w[8];
#pragma unroll
                for (int r = 0; r < 4; r++) a[r] = sIn[(rg + 16 * r) * 129 + kc * 16 + kk];
#pragma unroll
                for (int j = 0; j < 8; j++) w[j] = sW[kk * 128 + cg + 16 * j];
#pragma unroll
                for (int r = 0; r < 4; r++)
#pragma unroll
                    for (int j = 0; j < 8; j++) acc[r][j] = fmaf(a[r], w[j], acc[r][j]);
            }
            __syncthreads();
        }

        // epilogues
        if (mode == 3) {
            // stage relu vals then run-length pooled atomics (batch is sorted)
#pragma unroll
            for (int r = 0; r < 4; r++) {
                int rr = rg + 16 * r;
                if (sRow[rr] < 0) continue;
#pragma unroll
                for (int j = 0; j < 8; j++)
                    sIn[rr * 129 + cg + 16 * j] = fmaxf(acc[r][j] + bias[cg + 16 * j], 0.f);
            }
            __syncthreads();
            int col = t & 127, half = t >> 7;
            float s = 0.f; int cur = -1;
            for (int rr = half * 32; rr < half * 32 + 32; rr++) {
                int grow = sRow[rr]; if (grow < 0) continue;
                int m = grow / Nn, n = grow - m * Nn;
                int key = m * NGg + batch[n];
                if (key != cur) {
                    if (cur >= 0) atomicAdd(&g_hg[(size_t)cur * Dd + col], s);
                    cur = key; s = 0.f;
                }
                s += sIn[rr * 129 + col];
            }
            if (cur >= 0) atomicAdd(&g_hg[(size_t)cur * Dd + col], s);
        } else if (mode == 1) {
#pragma unroll
            for (int r = 0; r < 4; r++) {
                int grow = sRow[rg + 16 * r];
                float p = 0.f;
#pragma unroll
                for (int j = 0; j < 8; j++) {
                    float v = fmaxf(acc[r][j] + bias[cg + 16 * j], 0.f);
                    p = fmaf(v, Wd[cg + 16 * j], p);
                }
#pragma unroll
                for (int o = 8; o > 0; o >>= 1) p += __shfl_xor_sync(0xffffffffu, p, o);
                if (cg == 0 && grow >= 0) g_pred[grow] = p + bd[0];
            }
        } else {
            float* outp = outsel ? g_hB : g_hA;
#pragma unroll
            for (int r = 0; r < 4; r++) {
                int rr = rg + 16 * r; int grow = sRow[rr];
                if (grow < 0) continue;
#pragma unroll
                for (int j = 0; j < 8; j++) {
                    float v = fmaxf(acc[r][j] + bias[cg + 16 * j], 0.f);
                    outp[(size_t)grow * Dd + cg + 16 * j] = v;
                    if (mode == 0) outp[(size_t)(grow + Nn) * Dd + cg + 16 * j] = v;
                }
            }
        }
        __syncthreads();
    }
}

// ---------------- sampling kernels ----------------
__global__ void k_segmax(const int* __restrict__ batch) {
    int n = blockIdx.x * blockDim.x + threadIdx.x;
    if (n >= Nn) return;
    atomicMax(&g_mxbits[batch[n]], encf(g_pred[n]));
}

__global__ void k_segexp(const int* __restrict__ batch) {
    int n = blockIdx.x * blockDim.x + threadIdx.x;
    if (n >= Nn) return;
    int g = batch[n];
    float e = expf(g_pred[n] - decf(g_mxbits[g]));
    g_e[n] = e;
    atomicAdd(&g_ssum[g], e);
}

__global__ void k_score(const int* __restrict__ batch, unsigned fk0, unsigned fk1) {
    int n = blockIdx.x * blockDim.x + threadIdx.x;
    if (n >= Nn) return;
    int g = batch[n];
    float p = g_e[n] / g_ssum[g];
    float lp = logf(p + 1e-15f);
#pragma unroll
    for (int m = 0; m < Mm; m++) {
        unsigned x0 = 0u, x1 = (unsigned)(m * Nn + n);
        tf2x32(fk0, fk1, x0, x1);
        unsigned bits = x1;  // JAX partitionable threefry, low word
        float u = __uint_as_float((bits >> 9) | 0x3F800000u) - 1.0f;
        u = fmaxf(u, 0.0f);
        float gum = -logf(-logf(u + 1e-12f) + 1e-12f);
        float sc = lp + gum;
        g_score[m * Nn + n] = sc;
        atomicMax(&g_mx2bits[m * NGg + g], encf(sc));
    }
}

__global__ void k_argmin(const int* __restrict__ batch) {
    int idx = blockIdx.x * blockDim.x + threadIdx.x;
    if (idx >= Mm * Nn) return;
    int m = idx / Nn;
    int n = idx - m * Nn;
    int g = batch[n];
    float sc = g_score[idx];
    float mx = decf(g_mx2bits[m * NGg + g]);
    int cand = (sc >= mx) ? n : Nn;
    atomicMin(&g_raw[m * NGg + g], cand);
}

__global__ void k_buildflag() {
    int i = threadIdx.x;
    if (i >= Mm * NGg) return;
    int r = g_raw[i];
    if (r < Nn) {
        int m = i / NGg;
        g_flag[m * Nn + r] = 1;
        if (atomicExch(&g_amark[m * Nn + r], 1) == 0) {
            int p = atomicAdd(&g_naff, 1);
            g_alist[p] = m * Nn + r;
        }
    }
}

// mark rows whose layer-1 aggregation changes: dst of any edge with anchor src
__global__ void k_mark(const int* __restrict__ esrc, const int* __restrict__ edst) {
    int idx = blockIdx.x * blockDim.x + threadIdx.x;
    if (idx >= Mm * Ee) return;
    int m = idx / Ee;
    int e = idx - m * Ee;
    int s = esrc[e];
    if (g_flag[m * Nn + s]) {
        int d = edst[e];
        if (atomicExch(&g_amark[m * Nn + d], 1) == 0) {
            int p = atomicAdd(&g_naff, 1);
            g_alist[p] = m * Nn + d;
        }
    }
}

__global__ void k_buildx(const float* __restrict__ anchor_table) {
    int idx = blockIdx.x * blockDim.x + threadIdx.x;
    if (idx >= Mm * Nn * 32) return;
    int q = idx & 31;
    int mn = idx >> 5;
    int n = mn % Nn;
    float4 tv = *(const float4*)(g_tx + (size_t)n * Dd + q * 4);
    if (g_flag[mn]) {
        const float4 av = *(const float4*)(anchor_table + Dd + q * 4);  // row 1
        tv.x = fmaf(tv.x, av.x, tv.x);
        tv.y = fmaf(tv.y, av.y, tv.y);
        tv.z = fmaf(tv.z, av.z, tv.z);
        tv.w = fmaf(tv.w, av.w, tv.w);
    }
    *(float4*)(g_xM + (size_t)mn * Dd + q * 4) = tv;
}

__global__ void k_final(const float* __restrict__ Wp, const float* __restrict__ bp,
                        float* __restrict__ out) {
    __shared__ float red[128];
    int g = blockIdx.x, t = threadIdx.x;
    int c = g_counts[g]; if (c < 1) c = 1;
    float inv = 1.0f / (float)c;
    float hsum = (g_hg[(size_t)g * Dd + t] + g_hg[((size_t)NGg + g) * Dd + t]) * inv;
    for (int tt = 0; tt < 10; tt++) {
        red[t] = hsum * Wp[t * 10 + tt];
        __syncthreads();
        for (int off = 64; off > 0; off >>= 1) {
            if (t < off) red[t] += red[t + off];
            __syncthreads();
        }
        if (t == 0) out[g * 10 + tt] = red[0] * 0.5f + bp[tt];
        __syncthreads();
    }
}

// ---------------- launch ----------------
static inline int cdiv(int a, int b) { return (a + b - 1) / b; }

extern "C" void kernel_launch(void* const* d_in, const int* in_sizes, int n_in,
                              void* d_out, int out_size) {
    const int*   x_idx        = (const int*)d_in[0];
    const int*   esrc         = (const int*)d_in[1];
    const int*   edst         = (const int*)d_in[2];
    const int*   batch        = (const int*)d_in[3];
    const float* x_table      = (const float*)d_in[4];
    const float* anchor_table = (const float*)d_in[5];
    const float* Wg           = (const float*)d_in[6];
    const float* bg           = (const float*)d_in[7];
    const float* Wn           = (const float*)d_in[8];
    const float* bn           = (const float*)d_in[9];
    const float* Wd           = (const float*)d_in[10];
    const float* bd           = (const float*)d_in[11];
    const float* Wp           = (const float*)d_in[12];
    const float* bp           = (const float*)d_in[13];
    float* out = (float*)d_out;

    // fold_in(key(1), 1) on host
    unsigned fk0 = 0u, fk1 = 1u;
    tf2x32(0u, 1u, fk0, fk1);

    // setup
    k_reset<<<cdiv(Mm * Nn, 256), 256>>>();
    k_hist<<<cdiv(Ee, 256), 256>>>(edst);
    k_scan<<<1, 1024>>>();
    k_fill<<<cdiv(Ee, 256), 256>>>(esrc, edst);
    k_embed<<<cdiv(Nn * 32, 256), 256>>>(x_idx, x_table, batch);

    // pass1 L1: in=tx, gather, dual-write both m slices of g_hA
    k_fused<<<cdiv(Nn, 64), 256>>>(0, 1, 0, 0, Wg, bg, nullptr, nullptr, nullptr, Nn, 0);
    // pass1 L2 fused with pred epilogue (h2 never materialized)
    k_fused<<<cdiv(Nn, 64), 256>>>(2, 1, 1, 0, Wg + Dd * Dd, bg + Dd, Wd, bd, nullptr, Nn, 0);

    // anchor sampling
    k_segmax<<<cdiv(Nn, 256), 256>>>(batch);
    k_segexp<<<cdiv(Nn, 256), 256>>>(batch);
    k_score<<<cdiv(Nn, 256), 256>>>(batch, fk0, fk1);
    k_argmin<<<cdiv(Mm * Nn, 256), 256>>>(batch);
    k_buildflag<<<1, 256>>>();
    k_buildx<<<cdiv(Mm * Nn * 32, 256), 256>>>(anchor_table);
    k_mark<<<cdiv(Mm * Ee, 256), 256>>>(esrc, edst);

    // pass2 L1: only affected rows (anchors + their out-neighbors), in=g_xM -> patch g_hA
    k_fused<<<148, 256>>>(1, 1, 2, 0, Wg, bg, nullptr, nullptr, nullptr, 0, 1);
    // pass2 L2: full M*Nn, in=g_hA -> g_hB
    k_fused<<<cdiv(Mm * Nn, 64), 256>>>(2, 1, 2, 1, Wg + Dd * Dd, bg + Dd, nullptr, nullptr, nullptr, Mm * Nn, 0);
    // node MLP + fused smem-staged pooling
    k_fused<<<cdiv(Mm * Nn, 64), 256>>>(3, 0, 3, 0, Wn, bn, nullptr, nullptr, batch, Mm * Nn, 0);

    // final projection + mean over m
    k_final<<<NGg, 128>>>(Wp, bp, out);
}

// round 5
// speedup vs baseline: 1.4245x; 1.2169x over previous
#include <cuda_runtime.h>
#include <cstdint>

#define Nn  50000
#define Ee  800000
#define NGg 128
#define Dd  128
#define Mm  2

// ---------------- scratch ----------------
__device__ float g_tx[Nn * Dd];
__device__ float g_xM[Mm * Nn * Dd];
__device__ float g_hA[Mm * Nn * Dd];
__device__ float g_hB[Mm * Nn * Dd];
__device__ int   g_deg[Nn];
__device__ int   g_rowptr[Nn + 1];
__device__ int   g_cursor[Nn];
__device__ int   g_col[Ee];
__device__ float g_pred[Nn];
__device__ int   g_counts[NGg];
__device__ unsigned char g_flag[Mm * Nn];
__device__ float g_hg[Mm * NGg * Dd];
__device__ int   g_amark[Mm * Nn];
__device__ int   g_alist[Mm * Nn];
__device__ int   g_naff;

// ---------------- threefry2x32 ----------------
static __host__ __device__ inline unsigned rotl32(unsigned v, int r) {
    return (v << r) | (v >> (32 - r));
}
static __host__ __device__ inline void tf2x32(unsigned k0, unsigned k1,
                                              unsigned& x0, unsigned& x1) {
    unsigned k2 = k0 ^ k1 ^ 0x1BD11BDAu;
    x0 += k0; x1 += k1;
#define TFR(r) { x0 += x1; x1 = rotl32(x1, (r)); x1 ^= x0; }
    TFR(13) TFR(15) TFR(26) TFR(6)
    x0 += k1; x1 += k2 + 1u;
    TFR(17) TFR(29) TFR(16) TFR(24)
    x0 += k2; x1 += k0 + 2u;
    TFR(13) TFR(15) TFR(26) TFR(6)
    x0 += k0; x1 += k1 + 3u;
    TFR(17) TFR(29) TFR(16) TFR(24)
    x0 += k1; x1 += k2 + 4u;
    TFR(13) TFR(15) TFR(26) TFR(6)
    x0 += k2; x1 += k0 + 5u;
#undef TFR
}

static __device__ __forceinline__ uint32_t f2tf32(float f) {
    uint32_t r;
    asm("cvt.rna.tf32.f32 %0, %1;" : "=r"(r) : "f"(f));
    return r;
}

// ---------------- gather (MLP-unrolled) ----------------
static __device__ __forceinline__ float4 gather_row(const float* __restrict__ base,
                                                    int n, int lane, float4 acc) {
    int beg = g_rowptr[n], end = g_rowptr[n + 1];
    float4 a1 = make_float4(0.f, 0.f, 0.f, 0.f);
    float4 a2 = make_float4(0.f, 0.f, 0.f, 0.f);
    float4 a3 = make_float4(0.f, 0.f, 0.f, 0.f);
    for (int b0 = beg; b0 < end; b0 += 32) {
        int lim = end - b0; if (lim > 32) lim = 32;
        int cidx = (lane < lim) ? g_col[b0 + lane] : 0;
        int j = 0;
        for (; j + 4 <= lim; j += 4) {
            int s0 = __shfl_sync(0xffffffffu, cidx, j);
            int s1 = __shfl_sync(0xffffffffu, cidx, j + 1);
            int s2 = __shfl_sync(0xffffffffu, cidx, j + 2);
            int s3 = __shfl_sync(0xffffffffu, cidx, j + 3);
            float4 v0 = *(const float4*)(base + (size_t)s0 * Dd + lane * 4);
            float4 v1 = *(const float4*)(base + (size_t)s1 * Dd + lane * 4);
            float4 v2 = *(const float4*)(base + (size_t)s2 * Dd + lane * 4);
            float4 v3 = *(const float4*)(base + (size_t)s3 * Dd + lane * 4);
            acc.x += v0.x; acc.y += v0.y; acc.z += v0.z; acc.w += v0.w;
            a1.x += v1.x; a1.y += v1.y; a1.z += v1.z; a1.w += v1.w;
            a2.x += v2.x; a2.y += v2.y; a2.z += v2.z; a2.w += v2.w;
            a3.x += v3.x; a3.y += v3.y; a3.z += v3.z; a3.w += v3.w;
        }
        for (; j < lim; j++) {
            int s0 = __shfl_sync(0xffffffffu, cidx, j);
            float4 v0 = *(const float4*)(base + (size_t)s0 * Dd + lane * 4);
            acc.x += v0.x; acc.y += v0.y; acc.z += v0.z; acc.w += v0.w;
        }
    }
    acc.x += a1.x + a2.x + a3.x;
    acc.y += a1.y + a2.y + a3.y;
    acc.z += a1.z + a2.z + a3.z;
    acc.w += a1.w + a2.w + a3.w;
    return acc;
}

// ---------------- small kernels ----------------
__global__ void k_reset() {
    int i = blockIdx.x * blockDim.x + threadIdx.x;
    if (i < Mm * Nn) { g_flag[i] = 0; g_amark[i] = 0; }
    if (i < Nn) { g_deg[i] = 0; g_cursor[i] = 0; }
    if (i < Mm * NGg * Dd) g_hg[i] = 0.f;
    if (i < NGg) g_counts[i] = 0;
    if (i == 0) g_naff = 0;
}

__global__ void k_hist(const int* __restrict__ edst) {
    int e = blockIdx.x * blockDim.x + threadIdx.x;
    if (e < Ee) atomicAdd(&g_deg[edst[e]], 1);
}

__global__ void k_scan() {
    __shared__ int ss[1024];
    int tid = threadIdx.x;
    const int CH = (Nn + 1023) / 1024;
    int beg = tid * CH;
    int end = beg + CH; if (end > Nn) end = Nn;
    int s = 0;
    for (int i = beg; i < end; i++) s += g_deg[i];
    ss[tid] = s;
    __syncthreads();
    for (int off = 1; off < 1024; off <<= 1) {
        int v = (tid >= off) ? ss[tid - off] : 0;
        __syncthreads();
        ss[tid] += v;
        __syncthreads();
    }
    int base = (tid == 0) ? 0 : ss[tid - 1];
    for (int i = beg; i < end; i++) { g_rowptr[i] = base; base += g_deg[i]; }
    if (tid == 1023) g_rowptr[Nn] = ss[1023];
}

__global__ void k_fill(const int* __restrict__ esrc, const int* __restrict__ edst) {
    int e = blockIdx.x * blockDim.x + threadIdx.x;
    if (e >= Ee) return;
    int d = edst[e];
    int p = atomicAdd(&g_cursor[d], 1);
    g_col[g_rowptr[d] + p] = esrc[e];
}

__global__ void k_embed(const int* __restrict__ x_idx, const float* __restrict__ x_table,
                        const int* __restrict__ batch) {
    int idx = blockIdx.x * blockDim.x + threadIdx.x;
    if (idx >= Nn * 32) return;
    int n = idx >> 5, q = idx & 31;
    int xi = x_idx[n];
    float4 v = *(const float4*)(x_table + (size_t)xi * Dd + q * 4);
    *(float4*)(g_tx + (size_t)n * Dd + q * 4) = v;
    if (q == 0) atomicAdd(&g_counts[batch[n]], 1);
}

// ---------------- fp32 fused gather+GEMM (pass 1 exact + sparse patch) ----------------
// insel: 0=g_tx 1=g_xM 2=g_hA
// mode : 0 = relu out, dual-write both m slices of g_hA
//        1 = pred epilogue: g_pred[row] = relu(h)·Wd + bd
//        2 = relu out to g_hA (sparse patch)
__global__ __launch_bounds__(256) void k_fused(
    int insel, int mode,
    const float* __restrict__ W, const float* __restrict__ bias,
    const float* __restrict__ Wd, const float* __restrict__ bd,
    int nrows, int sparse)
{
    __shared__ float sIn[64 * 129];
    __shared__ float sW[16 * 128];
    __shared__ int sRow[64];
    const float* in = (insel == 0) ? g_tx : (insel == 1) ? g_xM : g_hA;
    int t = threadIdx.x, lane = t & 31, wid = t >> 5;
    int rg = t >> 4, cg = t & 15;
    int total = sparse ? g_naff : nrows;

    for (int tile = blockIdx.x; tile * 64 < total; tile += gridDim.x) {
        if (t < 64) {
            int idx = tile * 64 + t;
            sRow[t] = (idx < total) ? (sparse ? g_alist[idx] : idx) : -1;
        }
        __syncthreads();

        for (int rr = wid; rr < 64; rr += 8) {
            int grow = sRow[rr];
            float4 acc = make_float4(0.f, 0.f, 0.f, 0.f);
            if (grow >= 0) {
                int m = grow / Nn, n = grow - m * Nn;
                const float* base = in + (size_t)m * Nn * Dd;
                acc = *(const float4*)(base + (size_t)n * Dd + lane * 4);
                acc = gather_row(base, n, lane, acc);
            }
            float* d = &sIn[rr * 129 + lane * 4];
            d[0] = acc.x; d[1] = acc.y; d[2] = acc.z; d[3] = acc.w;
        }
        __syncthreads();

        float acc[4][8];
#pragma unroll
        for (int r = 0; r < 4; r++)
#pragma unroll
            for (int j = 0; j < 8; j++) acc[r][j] = 0.f;

        for (int kc = 0; kc < 8; kc++) {
            const float4* Ws = (const float4*)(W + kc * 16 * 128);
            ((float4*)sW)[t] = Ws[t];
            ((float4*)sW)[t + 256] = Ws[t + 256];
            __syncthreads();
#pragma unroll
            for (int kk = 0; kk < 16; kk++) {
                float a[4], w[8];
#pragma unroll
                for (int r = 0; r < 4; r++) a[r] = sIn[(rg + 16 * r) * 129 + kc * 16 + kk];
#pragma unroll
                for (int j = 0; j < 8; j++) w[j] = sW[kk * 128 + cg + 16 * j];
#pragma unroll
                for (int r = 0; r < 4; r++)
#pragma unroll
                    for (int j = 0; j < 8; j++) acc[r][j] = fmaf(a[r], w[j], acc[r][j]);
            }
            __syncthreads();
        }

        if (mode == 1) {
#pragma unroll
            for (int r = 0; r < 4; r++) {
                int grow = sRow[rg + 16 * r];
                float p = 0.f;
#pragma unroll
                for (int j = 0; j < 8; j++) {
                    float v = fmaxf(acc[r][j] + bias[cg + 16 * j], 0.f);
                    p = fmaf(v, Wd[cg + 16 * j], p);
                }
#pragma unroll
                for (int o = 8; o > 0; o >>= 1) p += __shfl_xor_sync(0xffffffffu, p, o);
                if (cg == 0 && grow >= 0) g_pred[grow] = p + bd[0];
            }
        } else {
#pragma unroll
            for (int r = 0; r < 4; r++) {
                int rr = rg + 16 * r; int grow = sRow[rr];
                if (grow < 0) continue;
#pragma unroll
                for (int j = 0; j < 8; j++) {
                    float v = fmaxf(acc[r][j] + bias[cg + 16 * j], 0.f);
                    g_hA[(size_t)grow * Dd + cg + 16 * j] = v;
                    if (mode == 0) g_hA[(size_t)(grow + Nn) * Dd + cg + 16 * j] = v;
                }
            }
        }
        __syncthreads();
    }
}

// ---------------- tf32 mma.sync GEMM: 64 rows x 128 cols per tile ----------------
// smem: sW [128][136] (tf32 bits), sIn [64][132] (tf32 bits), sRow[64]
#define SW_STR 136
#define SI_STR 132
#define SMEM_MMA ((128 * SW_STR + 64 * SI_STR) * 4 + 64 * 4)

static __device__ __forceinline__ void mma_tf32(float* c, const uint32_t* a, const uint32_t* b) {
    asm volatile(
        "mma.sync.aligned.m16n8k8.row.col.f32.tf32.tf32.f32 "
        "{%0,%1,%2,%3}, {%4,%5,%6,%7}, {%8,%9}, {%0,%1,%2,%3};"
        : "+f"(c[0]), "+f"(c[1]), "+f"(c[2]), "+f"(c[3])
        : "r"(a[0]), "r"(a[1]), "r"(a[2]), "r"(a[3]), "r"(b[0]), "r"(b[1]));
}

__global__ __launch_bounds__(256) void k_mma(
    int gather, int pool, int insel,
    const float* __restrict__ W, const float* __restrict__ bias,
    const int* __restrict__ batch, int nrows)
{
    extern __shared__ float sm[];
    float* sW = sm;
    float* sIn = sm + 128 * SW_STR;
    int* sRow = (int*)(sIn + 64 * SI_STR);
    const float* in = (insel == 2) ? g_hA : g_hB;
    int t = threadIdx.x, lane = t & 31, wid = t >> 5;
    int gid = lane >> 2, tig = lane & 3;
    int wr = wid >> 2, wc = wid & 3;   // warp grid 2 x 4 (32 rows x 32 cols each)

    // stage W (tf32 bits): sW[k][c] = tf32(W[k*128+c])
    for (int idx = t; idx < 16384; idx += 256) {
        int k = idx >> 7, c = idx & 127;
        sW[k * SW_STR + c] = __uint_as_float(f2tf32(W[idx]));
    }

    int ntile = (nrows + 63) >> 6;
    for (int tile = blockIdx.x; tile < ntile; tile += gridDim.x) {
        if (t < 64) {
            int idx = tile * 64 + t;
            sRow[t] = (idx < nrows) ? idx : -1;
        }
        __syncthreads();

        // stage input rows (gathered), tf32-converted
        for (int rr = wid; rr < 64; rr += 8) {
            int grow = sRow[rr];
            float4 acc = make_float4(0.f, 0.f, 0.f, 0.f);
            if (grow >= 0) {
                int m = grow / Nn, n = grow - m * Nn;
                const float* base = in + (size_t)m * Nn * Dd;
                acc = *(const float4*)(base + (size_t)n * Dd + lane * 4);
                if (gather) acc = gather_row(base, n, lane, acc);
            }
            float* d = &sIn[rr * SI_STR + lane * 4];
            d[0] = __uint_as_float(f2tf32(acc.x));
            d[1] = __uint_as_float(f2tf32(acc.y));
            d[2] = __uint_as_float(f2tf32(acc.z));
            d[3] = __uint_as_float(f2tf32(acc.w));
        }
        __syncthreads();

        float c_[2][4][4];
#pragma unroll
        for (int mt = 0; mt < 2; mt++)
#pragma unroll
            for (int nt = 0; nt < 4; nt++)
#pragma unroll
                for (int q = 0; q < 4; q++) c_[mt][nt][q] = 0.f;

#pragma unroll 4
        for (int ks = 0; ks < 16; ks++) {
            int k0 = ks * 8;
            uint32_t a[2][4], b[4][2];
#pragma unroll
            for (int mt = 0; mt < 2; mt++) {
                const float* Ap = sIn + (wr * 32 + mt * 16 + gid) * SI_STR + k0 + tig;
                a[mt][0] = __float_as_uint(Ap[0]);
                a[mt][1] = __float_as_uint(Ap[8 * SI_STR]);
                a[mt][2] = __float_as_uint(Ap[4]);
                a[mt][3] = __float_as_uint(Ap[8 * SI_STR + 4]);
            }
#pragma unroll
            for (int nt = 0; nt < 4; nt++) {
                const float* Bp = sW + (k0 + tig) * SW_STR + wc * 32 + nt * 8 + gid;
                b[nt][0] = __float_as_uint(Bp[0]);
                b[nt][1] = __float_as_uint(Bp[4 * SW_STR]);
            }
#pragma unroll
            for (int mt = 0; mt < 2; mt++)
#pragma unroll
                for (int nt = 0; nt < 4; nt++)
                    mma_tf32(c_[mt][nt], a[mt], b[nt]);
        }
        __syncthreads();

        // stage relu(acc + bias) into sIn as [64][SI_STR] fp32
#pragma unroll
        for (int mt = 0; mt < 2; mt++) {
#pragma unroll
            for (int nt = 0; nt < 4; nt++) {
                int col = wc * 32 + nt * 8 + tig * 2;
                int row = wr * 32 + mt * 16 + gid;
                float b0 = bias[col], b1 = bias[col + 1];
                sIn[row * SI_STR + col]           = fmaxf(c_[mt][nt][0] + b0, 0.f);
                sIn[row * SI_STR + col + 1]       = fmaxf(c_[mt][nt][1] + b1, 0.f);
                sIn[(row + 8) * SI_STR + col]     = fmaxf(c_[mt][nt][2] + b0, 0.f);
                sIn[(row + 8) * SI_STR + col + 1] = fmaxf(c_[mt][nt][3] + b1, 0.f);
            }
        }
        __syncthreads();

        if (pool) {
            int col = t & 127, half = t >> 7;
            float s = 0.f; int cur = -1;
            for (int rr = half * 32; rr < half * 32 + 32; rr++) {
                int grow = sRow[rr]; if (grow < 0) continue;
                int m = grow / Nn;
                int key = m * NGg + batch[grow - m * Nn];
                if (key != cur) {
                    if (cur >= 0) atomicAdd(&g_hg[(size_t)cur * Dd + col], s);
                    cur = key; s = 0.f;
                }
                s += sIn[rr * SI_STR + col];
            }
            if (cur >= 0) atomicAdd(&g_hg[(size_t)cur * Dd + col], s);
        } else {
            for (int idx = t; idx < 2048; idx += 256) {
                int rr = idx >> 5, q = idx & 31;
                int grow = sRow[rr];
                if (grow < 0) continue;
                *(float4*)(g_hB + (size_t)grow * Dd + q * 4) =
                    *(float4*)(sIn + rr * SI_STR + q * 4);
            }
        }
        __syncthreads();
    }
}

// ---------------- fused per-graph sampling ----------------
static __device__ __forceinline__ float score_fn(int n, int m, float mx, float ssum,
                                                 unsigned fk0, unsigned fk1) {
    float e = expf(g_pred[n] - mx);
    float p = e / ssum;
    float lp = logf(p + 1e-15f);
    unsigned x0 = 0u, x1 = (unsigned)(m * Nn + n);
    tf2x32(fk0, fk1, x0, x1);
    float u = __uint_as_float((x1 >> 9) | 0x3F800000u) - 1.0f;
    u = fmaxf(u, 0.0f);
    float gum = -logf(-logf(u + 1e-12f) + 1e-12f);
    return lp + gum;
}

__global__ void k_sample(const int* __restrict__ batch, unsigned fk0, unsigned fk1) {
    __shared__ float fb[8];
    __shared__ int ib[8];
    __shared__ int sSE[2];
    __shared__ float sMx, sSum, sBest;
    int g = blockIdx.x, t = threadIdx.x, lane = t & 31, wid = t >> 5;
    if (t < 2) {
        int tgt = g + t;
        int lo = 0, hi = Nn;
        while (lo < hi) { int mid = (lo + hi) >> 1; if (batch[mid] < tgt) lo = mid + 1; else hi = mid; }
        sSE[t] = lo;
    }
    __syncthreads();
    int s0 = sSE[0], s1 = sSE[1];

    float mx = -3.4e38f;
    for (int n = s0 + t; n < s1; n += 256) mx = fmaxf(mx, g_pred[n]);
#pragma unroll
    for (int o = 16; o > 0; o >>= 1) mx = fmaxf(mx, __shfl_xor_sync(0xffffffffu, mx, o));
    if (lane == 0) fb[wid] = mx;
    __syncthreads();
    if (t == 0) { float x = fb[0]; for (int i = 1; i < 8; i++) x = fmaxf(x, fb[i]); sMx = x; }
    __syncthreads();
    float gmx = sMx;

    float sm = 0.f;
    for (int n = s0 + t; n < s1; n += 256) sm += expf(g_pred[n] - gmx);
#pragma unroll
    for (int o = 16; o > 0; o >>= 1) sm += __shfl_xor_sync(0xffffffffu, sm, o);
    if (lane == 0) fb[wid] = sm;
    __syncthreads();
    if (t == 0) { float x = 0.f; for (int i = 0; i < 8; i++) x += fb[i]; sSum = x; }
    __syncthreads();
    float gsum = sSum;

    for (int m = 0; m < Mm; m++) {
        float best = -3.4e38f;
        for (int n = s0 + t; n < s1; n += 256)
            best = fmaxf(best, score_fn(n, m, gmx, gsum, fk0, fk1));
#pragma unroll
        for (int o = 16; o > 0; o >>= 1) best = fmaxf(best, __shfl_xor_sync(0xffffffffu, best, o));
        if (lane == 0) fb[wid] = best;
        __syncthreads();
        if (t == 0) { float x = fb[0]; for (int i = 1; i < 8; i++) x = fmaxf(x, fb[i]); sBest = x; }
        __syncthreads();
        float gb = sBest;
        __syncthreads();

        int cand = Nn;
        for (int n = s0 + t; n < s1; n += 256)
            if (score_fn(n, m, gmx, gsum, fk0, fk1) >= gb) cand = min(cand, n);
#pragma unroll
        for (int o = 16; o > 0; o >>= 1) cand = min(cand, __shfl_xor_sync(0xffffffffu, cand, o));
        if (lane == 0) ib[wid] = cand;
        __syncthreads();
        if (t == 0) {
            int x = ib[0]; for (int i = 1; i < 8; i++) x = min(x, ib[i]);
            if (x < Nn) {
                g_flag[m * Nn + x] = 1;
                if (atomicExch(&g_amark[m * Nn + x], 1) == 0) {
                    int p = atomicAdd(&g_naff, 1);
                    g_alist[p] = m * Nn + x;
                }
            }
        }
        __syncthreads();
    }
}

__global__ void k_mark(const int* __restrict__ esrc, const int* __restrict__ edst) {
    int idx = blockIdx.x * blockDim.x + threadIdx.x;
    if (idx >= Mm * Ee) return;
    int m = idx / Ee;
    int e = idx - m * Ee;
    int s = esrc[e];
    if (g_flag[m * Nn + s]) {
        int d = edst[e];
        if (atomicExch(&g_amark[m * Nn + d], 1) == 0) {
            int p = atomicAdd(&g_naff, 1);
            g_alist[p] = m * Nn + d;
        }
    }
}

__global__ void k_buildx(const float* __restrict__ anchor_table) {
    int idx = blockIdx.x * blockDim.x + threadIdx.x;
    if (idx >= Mm * Nn * 32) return;
    int q = idx & 31;
    int mn = idx >> 5;
    int n = mn % Nn;
    float4 tv = *(const float4*)(g_tx + (size_t)n * Dd + q * 4);
    if (g_flag[mn]) {
        const float4 av = *(const float4*)(anchor_table + Dd + q * 4);
        tv.x = fmaf(tv.x, av.x, tv.x);
        tv.y = fmaf(tv.y, av.y, tv.y);
        tv.z = fmaf(tv.z, av.z, tv.z);
        tv.w = fmaf(tv.w, av.w, tv.w);
    }
    *(float4*)(g_xM + (size_t)mn * Dd + q * 4) = tv;
}

__global__ void k_final(const float* __restrict__ Wp, const float* __restrict__ bp,
                        float* __restrict__ out) {
    __shared__ float red[128];
    int g = blockIdx.x, t = threadIdx.x;
    int c = g_counts[g]; if (c < 1) c = 1;
    float inv = 1.0f / (float)c;
    float hsum = (g_hg[(size_t)g * Dd + t] + g_hg[((size_t)NGg + g) * Dd + t]) * inv;
    for (int tt = 0; tt < 10; tt++) {
        red[t] = hsum * Wp[t * 10 + tt];
        __syncthreads();
        for (int off = 64; off > 0; off >>= 1) {
            if (t < off) red[t] += red[t + off];
            __syncthreads();
        }
        if (t == 0) out[g * 10 + tt] = red[0] * 0.5f + bp[tt];
        __syncthreads();
    }
}

// ---------------- launch ----------------
static inline int cdiv(int a, int b) { return (a + b - 1) / b; }

extern "C" void kernel_launch(void* const* d_in, const int* in_sizes, int n_in,
                              void* d_out, int out_size) {
    const int*   x_idx        = (const int*)d_in[0];
    const int*   esrc         = (const int*)d_in[1];
    const int*   edst         = (const int*)d_in[2];
    const int*   batch        = (const int*)d_in[3];
    const float* x_table      = (const float*)d_in[4];
    const float* anchor_table = (const float*)d_in[5];
    const float* Wg           = (const float*)d_in[6];
    const float* bg           = (const float*)d_in[7];
    const float* Wn           = (const float*)d_in[8];
    const float* bn           = (const float*)d_in[9];
    const float* Wd           = (const float*)d_in[10];
    const float* bd           = (const float*)d_in[11];
    const float* Wp           = (const float*)d_in[12];
    const float* bp           = (const float*)d_in[13];
    float* out = (float*)d_out;

    unsigned fk0 = 0u, fk1 = 1u;
    tf2x32(0u, 1u, fk0, fk1);

    static int smem_set = 0;
    if (!smem_set) {
        cudaFuncSetAttribute(k_mma, cudaFuncAttributeMaxDynamicSharedMemorySize, SMEM_MMA);
        smem_set = 1;
    }

    // setup
    k_reset<<<cdiv(Mm * Nn, 256), 256>>>();
    k_hist<<<cdiv(Ee, 256), 256>>>(edst);
    k_scan<<<1, 1024>>>();
    k_fill<<<cdiv(Ee, 256), 256>>>(esrc, edst);
    k_embed<<<cdiv(Nn * 32, 256), 256>>>(x_idx, x_table, batch);

    // pass1 (fp32, exact): L1 dual-write g_hA; L2 fused pred epilogue
    k_fused<<<cdiv(Nn, 64), 256>>>(0, 0, Wg, bg, nullptr, nullptr, Nn, 0);
    k_fused<<<cdiv(Nn, 64), 256>>>(2, 1, Wg + Dd * Dd, bg + Dd, Wd, bd, Nn, 0);

    // anchor sampling
    k_sample<<<NGg, 256>>>(batch, fk0, fk1);
    k_buildx<<<cdiv(Mm * Nn * 32, 256), 256>>>(anchor_table);
    k_mark<<<cdiv(Mm * Ee, 256), 256>>>(esrc, edst);

    // pass2 L1: sparse patch of g_hA (fp32, exact)
    k_fused<<<148, 256>>>(1, 2, Wg, bg, nullptr, nullptr, 0, 1);

    // pass2 L2 (tf32 mma.sync): g_hA -> g_hB
    k_mma<<<296, 256, SMEM_MMA>>>(1, 0, 2, Wg + Dd * Dd, bg + Dd, batch, Mm * Nn);
    // node MLP + pooled epilogue (tf32): g_hB -> g_hg
    k_mma<<<296, 256, SMEM_MMA>>>(0, 1, 3, Wn, bn, batch, Mm * Nn);

    // final projection + mean over m
    k_final<<<NGg, 128>>>(Wp, bp, out);
}